// round 15
// baseline (speedup 1.0000x reference)
#include <cuda_runtime.h>
#include <cuda_fp16.h>
#include <mma.h>
#include <cstdint>

using namespace nvcuda;

#define B_    16
#define H_    8
#define N_    1024
#define DIM_  512
#define KD_   32
#define D_    128
#define BH_   (B_*H_)

// ---- scratch (device globals; no allocations allowed) ----
__device__ __align__(16) __half g_qh[(size_t)BH_ * N_ * KD_];       // [bh][n][kd] (scaled by log2e/sqrt(32))
__device__ __align__(16) __half g_kh[(size_t)BH_ * N_ * KD_];       // [bh][n][kd]
__device__ __align__(16) __half g_vh[(size_t)BH_ * D_ * N_];        // [bh][d][n]
__device__ __align__(16) __half g_oh[(size_t)B_ * N_ * (H_*D_)];    // [b][n][c]
__device__ __align__(16) __half g_pwh[(size_t)DIM_ * (H_*D_)];      // [oc][c]
__device__ __align__(16) __half g_qwh[(size_t)H_ * 192 * 64];       // [h][o][c]

// cp.async helpers
__device__ __forceinline__ void cpa16(void* dst_smem, const void* src_gmem) {
    uint32_t d = (uint32_t)__cvta_generic_to_shared(dst_smem);
    asm volatile("cp.async.cg.shared.global [%0], [%1], 16;" :: "r"(d), "l"(src_gmem));
}
#define CPA_COMMIT()  asm volatile("cp.async.commit_group;" ::: "memory")
#define CPA_WAIT(n)   asm volatile("cp.async.wait_group %0;" :: "n"(n) : "memory")

// raw mma / ldmatrix / ex2
__device__ __forceinline__ void ldsm4(uint32_t& r0, uint32_t& r1, uint32_t& r2, uint32_t& r3,
                                      uint32_t addr) {
    asm volatile("ldmatrix.sync.aligned.m8n8.x4.shared.b16 {%0,%1,%2,%3}, [%4];"
                 : "=r"(r0), "=r"(r1), "=r"(r2), "=r"(r3) : "r"(addr));
}
__device__ __forceinline__ void mma16816(float* c, uint32_t a0, uint32_t a1, uint32_t a2,
                                         uint32_t a3, uint32_t b0, uint32_t b1) {
    asm volatile("mma.sync.aligned.m16n8k16.row.col.f32.f16.f16.f32 "
                 "{%0,%1,%2,%3}, {%4,%5,%6,%7}, {%8,%9}, {%0,%1,%2,%3};"
                 : "+f"(c[0]), "+f"(c[1]), "+f"(c[2]), "+f"(c[3])
                 : "r"(a0), "r"(a1), "r"(a2), "r"(a3), "r"(b0), "r"(b1));
}
__device__ __forceinline__ float ex2f(float x) {
    float r; asm("ex2.approx.f32 %0, %1;" : "=f"(r) : "f"(x)); return r;
}

// ======================================================================
// Kernel 0a/0b: weight converts fp32 -> fp16
// ======================================================================
__global__ __launch_bounds__(256) void k_cvt_pw(const float* __restrict__ pw) {
    int idx = blockIdx.x * 256 + threadIdx.x;
    float4 v = ((const float4*)pw)[idx];
    __half2* d = (__half2*)g_pwh;
    d[idx * 2 + 0] = __floats2half2_rn(v.x, v.y);
    d[idx * 2 + 1] = __floats2half2_rn(v.z, v.w);
}
__global__ __launch_bounds__(256) void k_cvt_qw(const float* __restrict__ qw) {
    int idx = blockIdx.x * 256 + threadIdx.x;
    float4 v = ((const float4*)qw)[idx];
    __half2* d = (__half2*)g_qwh;
    d[idx * 2 + 0] = __floats2half2_rn(v.x, v.y);
    d[idx * 2 + 1] = __floats2half2_rn(v.z, v.w);
}

// ======================================================================
// Kernel 1: grouped 1x1 conv (QKV) via wmma (q scale folds log2e).
// ======================================================================
#define QK_WLD  72
#define QK_XLD  136
#define QK_CLD  132
#define QK_OFF_XS 27648
#define QK_SMEM_REQ (192 * QK_CLD * 4)

__global__ __launch_bounds__(256) void k_qkv(const float* __restrict__ x,
                                             const float* __restrict__ bias) {
    extern __shared__ __align__(16) char smraw[];
    __half* Ws = (__half*)smraw;
    __half* Xs = (__half*)(smraw + QK_OFF_XS);
    float*  Cs = (float*)smraw;

    int bh = blockIdx.y;
    int b = bh >> 3, h = bh & 7;
    int n0 = blockIdx.x * 128;
    int tid = threadIdx.x;
    int wid = tid >> 5;
    int warp_m = wid >> 1, warp_n = wid & 1;

    const __half* Wh = g_qwh + (size_t)h * 192 * 64;
    const float*  Xg = x + ((size_t)b * DIM_ + h * 64) * N_;

#pragma unroll
    for (int i = 0; i < 6; i++) {
        int idx = tid + i * 256;
        int row = idx >> 3, ch = idx & 7;
        cpa16(&Ws[row * QK_WLD + ch * 8], &Wh[(size_t)row * 64 + ch * 8]);
    }
    CPA_COMMIT();

#pragma unroll
    for (int i = 0; i < 4; i++) {
        int idx = tid + i * 256;
        int row = idx >> 4, g = idx & 15;
        const float4* src = (const float4*)&Xg[(size_t)row * N_ + n0 + g * 8];
        float4 v0 = src[0], v1 = src[1];
        __half2* dst = (__half2*)&Xs[row * QK_XLD + g * 8];
        dst[0] = __floats2half2_rn(v0.x, v0.y);
        dst[1] = __floats2half2_rn(v0.z, v0.w);
        dst[2] = __floats2half2_rn(v1.x, v1.y);
        dst[3] = __floats2half2_rn(v1.z, v1.w);
    }
    CPA_WAIT(0);
    __syncthreads();

    wmma::fragment<wmma::accumulator, 16, 16, 16, float> acc[3][4];
#pragma unroll
    for (int i = 0; i < 3; i++)
#pragma unroll
        for (int j = 0; j < 4; j++)
            wmma::fill_fragment(acc[i][j], 0.0f);

#pragma unroll
    for (int ks = 0; ks < 4; ks++) {
        wmma::fragment<wmma::matrix_a, 16, 16, 16, __half, wmma::row_major> a[3];
        wmma::fragment<wmma::matrix_b, 16, 16, 16, __half, wmma::row_major> bf[4];
#pragma unroll
        for (int i = 0; i < 3; i++)
            wmma::load_matrix_sync(a[i], &Ws[(warp_m * 48 + i * 16) * QK_WLD + ks * 16], QK_WLD);
#pragma unroll
        for (int j = 0; j < 4; j++)
            wmma::load_matrix_sync(bf[j], &Xs[(ks * 16) * QK_XLD + warp_n * 64 + j * 16], QK_XLD);
#pragma unroll
        for (int i = 0; i < 3; i++)
#pragma unroll
            for (int j = 0; j < 4; j++)
                wmma::mma_sync(acc[i][j], a[i], bf[j], acc[i][j]);
    }
    __syncthreads();

#pragma unroll
    for (int i = 0; i < 3; i++)
#pragma unroll
        for (int j = 0; j < 4; j++)
            wmma::store_matrix_sync(&Cs[(warp_m * 48 + i * 16) * QK_CLD + warp_n * 64 + j * 16],
                                    acc[i][j], QK_CLD, wmma::mem_row_major);
    __syncthreads();

    // log2(e)/sqrt(32): softmax done base-2 downstream
    const float SCALE = 0.2550348564624786f;
#pragma unroll
    for (int t = 0; t < 3; t++) {
        int item = tid + t * 256;
        int og = item >> 4, ng = item & 15;
        int oo0 = og * 4;
        int n = n0 + ng * 8;
        float bb[4];
#pragma unroll
        for (int r = 0; r < 4; r++) bb[r] = bias[h * 192 + oo0 + r];

        if (oo0 < 32) {
#pragma unroll
            for (int j = 0; j < 8; j++) {
                float v0 = (Cs[(oo0 + 0) * QK_CLD + ng * 8 + j] + bb[0]) * SCALE;
                float v1 = (Cs[(oo0 + 1) * QK_CLD + ng * 8 + j] + bb[1]) * SCALE;
                float v2 = (Cs[(oo0 + 2) * QK_CLD + ng * 8 + j] + bb[2]) * SCALE;
                float v3 = (Cs[(oo0 + 3) * QK_CLD + ng * 8 + j] + bb[3]) * SCALE;
                __half2* dst = (__half2*)&g_qh[((size_t)bh * N_ + n + j) * KD_ + oo0];
                dst[0] = __floats2half2_rn(v0, v1);
                dst[1] = __floats2half2_rn(v2, v3);
            }
        } else if (oo0 < 64) {
#pragma unroll
            for (int j = 0; j < 8; j++) {
                float v0 = Cs[(oo0 + 0) * QK_CLD + ng * 8 + j] + bb[0];
                float v1 = Cs[(oo0 + 1) * QK_CLD + ng * 8 + j] + bb[1];
                float v2 = Cs[(oo0 + 2) * QK_CLD + ng * 8 + j] + bb[2];
                float v3 = Cs[(oo0 + 3) * QK_CLD + ng * 8 + j] + bb[3];
                __half2* dst = (__half2*)&g_kh[((size_t)bh * N_ + n + j) * KD_ + (oo0 - 32)];
                dst[0] = __floats2half2_rn(v0, v1);
                dst[1] = __floats2half2_rn(v2, v3);
            }
        } else {
#pragma unroll
            for (int r = 0; r < 4; r++) {
                const float* cr = &Cs[(oo0 + r) * QK_CLD + ng * 8];
                __half2* dst = (__half2*)&g_vh[((size_t)bh * D_ + (oo0 + r - 64)) * N_ + n];
                dst[0] = __floats2half2_rn(cr[0] + bb[r], cr[1] + bb[r]);
                dst[1] = __floats2half2_rn(cr[2] + bb[r], cr[3] + bb[r]);
                dst[2] = __floats2half2_rn(cr[4] + bb[r], cr[5] + bb[r]);
                dst[3] = __floats2half2_rn(cr[6] + bb[r], cr[7] + bb[r]);
            }
        }
    }
}

// ======================================================================
// Kernel 2: FUSED attention, FA2-style raw mma.
// NOW: each warp owns m32 (two m16 halves) x full 128 d -> every K/V
// ldsm.x4 feeds 4 mma instead of 2 (smem crossbar pressure halves).
// CTA covers 256 m-rows; grid 512; 8 warps, 1 CTA/SM (~185 regs).
// smem: Qs[256][40] @0 (20480) | Ks0 @20480 | Ks1 @30720
//       | Vs0[128][136] @40960 | Vs1 @75776 -> 110592 B.
// ======================================================================
#define AT_OFF_KS0 20480
#define AT_OFF_KS1 30720
#define AT_OFF_VS0 40960
#define AT_OFF_VS1 75776
#define AT_SMEM_REQ 110592

__global__ __launch_bounds__(256) void k_attn() {
    extern __shared__ __align__(16) char smraw[];

    int bh = blockIdx.y;
    int b = bh >> 3, h = bh & 7;
    int m0 = blockIdx.x * 256;
    int tid = threadIdx.x;
    int w = tid >> 5, lane = tid & 31;
    int i8 = lane & 7, sub = lane >> 3;
    int g = lane >> 2, tg = lane & 3;

    const __half* Qh = g_qh + (size_t)bh * N_ * KD_;
    const __half* Kh = g_kh + (size_t)bh * N_ * KD_;
    const __half* Vh = g_vh + (size_t)bh * D_ * N_;

    uint32_t sm32 = (uint32_t)__cvta_generic_to_shared(smraw);
    uint32_t ks32b = sm32 + AT_OFF_KS0;
    uint32_t vs32b = sm32 + AT_OFF_VS0;

    // ldmatrix lane offsets (bytes)
    uint32_t qoff = (((sub & 1) * 8 + i8) * 40 + (sub >> 1) * 8) * 2;  // A: Q m16k16
    uint32_t koff = ((i8) * 40 + sub * 8) * 2;                         // B: K n-tile
    uint32_t voff = (((sub >> 1) * 8 + i8) * 136 + (sub & 1) * 8) * 2; // B: V d-pair

    // ---- prologue staging: g0 = {Q, K0, V0}, g1 = {K1, V1} ----
    {
        // Q: 256 rows x 4 segs = 1024 cpa16
#pragma unroll
        for (int i = 0; i < 4; i++) {
            int item = tid + i * 256;
            int row = item >> 2, seg = item & 3;
            cpa16(smraw + (row * 40 + seg * 8) * 2, &Qh[(size_t)(m0 + row) * KD_ + seg * 8]);
        }
        int idx = tid * 2;
#pragma unroll
        for (int i = 0; i < 2; i++) {
            int row = (idx + i) >> 2, seg = (idx + i) & 3;
            cpa16(smraw + AT_OFF_KS0 + (row * 40 + seg * 8) * 2,
                  &Kh[(size_t)row * KD_ + seg * 8]);
        }
#pragma unroll
        for (int i = 0; i < 8; i++) {
            int vi = tid + i * 256;
            int d = vi >> 4, seg = vi & 15;
            cpa16(smraw + AT_OFF_VS0 + (d * 136 + seg * 8) * 2,
                  &Vh[(size_t)d * N_ + seg * 8]);
        }
        CPA_COMMIT();
#pragma unroll
        for (int i = 0; i < 2; i++) {
            int row = (idx + i) >> 2, seg = (idx + i) & 3;
            cpa16(smraw + AT_OFF_KS1 + (row * 40 + seg * 8) * 2,
                  &Kh[(size_t)(128 + row) * KD_ + seg * 8]);
        }
#pragma unroll
        for (int i = 0; i < 8; i++) {
            int vi = tid + i * 256;
            int d = vi >> 4, seg = vi & 15;
            cpa16(smraw + AT_OFF_VS1 + (d * 136 + seg * 8) * 2,
                  &Vh[(size_t)d * N_ + 128 + seg * 8]);
        }
        CPA_COMMIT();
    }

    float oacc0[16][4], oacc1[16][4];     // m-half 0 / 1
#pragma unroll
    for (int t = 0; t < 16; t++) {
        oacc0[t][0] = 0.f; oacc0[t][1] = 0.f; oacc0[t][2] = 0.f; oacc0[t][3] = 0.f;
        oacc1[t][0] = 0.f; oacc1[t][1] = 0.f; oacc1[t][2] = 0.f; oacc1[t][3] = 0.f;
    }
    float rs0_lo = 0.f, rs0_hi = 0.f, rs1_lo = 0.f, rs1_hi = 0.f;

    // Q fragments (persist whole kernel): two m16 halves
    uint32_t qa[8], qb[8];
    CPA_WAIT(1);
    __syncthreads();
    {
        uint32_t qbase0 = sm32 + (uint32_t)(w * 32 * 40 * 2) + qoff;
        uint32_t qbase1 = qbase0 + 16 * 40 * 2;
        ldsm4(qa[0], qa[1], qa[2], qa[3], qbase0);
        ldsm4(qa[4], qa[5], qa[6], qa[7], qbase0 + 32);
        ldsm4(qb[0], qb[1], qb[2], qb[3], qbase1);
        ldsm4(qb[4], qb[5], qb[6], qb[7], qbase1 + 32);
    }

#pragma unroll 1
    for (int nc = 0; nc < 8; nc++) {
        if (nc == 7) { CPA_WAIT(0); } else { CPA_WAIT(1); }
        __syncthreads();

        uint32_t kcur = ks32b + (uint32_t)((nc & 1) * 10240);
        uint32_t vcur = vs32b + (uint32_t)((nc & 1) * 34816);

        // ---- per k-step: S for 2 n8-tiles x 2 m-halves -> exp -> O sweep ----
#pragma unroll
        for (int ks = 0; ks < 8; ks++) {
            uint32_t kb0, kb1, kb2, kb3, kc0, kc1, kc2, kc3;
            ldsm4(kb0, kb1, kb2, kb3, kcur + (uint32_t)((2 * ks) * 640) + koff);
            ldsm4(kc0, kc1, kc2, kc3, kcur + (uint32_t)((2 * ks + 1) * 640) + koff);
            float c00[4] = {0.f, 0.f, 0.f, 0.f};   // mhalf0, tile0
            float c01[4] = {0.f, 0.f, 0.f, 0.f};   // mhalf0, tile1
            float c10[4] = {0.f, 0.f, 0.f, 0.f};   // mhalf1, tile0
            float c11[4] = {0.f, 0.f, 0.f, 0.f};   // mhalf1, tile1
            mma16816(c00, qa[0], qa[1], qa[2], qa[3], kb0, kb1);
            mma16816(c00, qa[4], qa[5], qa[6], qa[7], kb2, kb3);
            mma16816(c01, qa[0], qa[1], qa[2], qa[3], kc0, kc1);
            mma16816(c01, qa[4], qa[5], qa[6], qa[7], kc2, kc3);
            mma16816(c10, qb[0], qb[1], qb[2], qb[3], kb0, kb1);
            mma16816(c10, qb[4], qb[5], qb[6], qb[7], kb2, kb3);
            mma16816(c11, qb[0], qb[1], qb[2], qb[3], kc0, kc1);
            mma16816(c11, qb[4], qb[5], qb[6], qb[7], kc2, kc3);

            float e0 = ex2f(c00[0]), e1 = ex2f(c00[1]), e2 = ex2f(c00[2]), e3 = ex2f(c00[3]);
            float f0 = ex2f(c01[0]), f1 = ex2f(c01[1]), f2 = ex2f(c01[2]), f3 = ex2f(c01[3]);
            float u0 = ex2f(c10[0]), u1 = ex2f(c10[1]), u2 = ex2f(c10[2]), u3 = ex2f(c10[3]);
            float v0 = ex2f(c11[0]), v1 = ex2f(c11[1]), v2 = ex2f(c11[2]), v3 = ex2f(c11[3]);
            rs0_lo += (e0 + e1) + (f0 + f1);
            rs0_hi += (e2 + e3) + (f2 + f3);
            rs1_lo += (u0 + u1) + (v0 + v1);
            rs1_hi += (u2 + u3) + (v2 + v3);
            __half2 h0 = __floats2half2_rn(e0, e1);
            __half2 h1 = __floats2half2_rn(e2, e3);
            __half2 h2 = __floats2half2_rn(f0, f1);
            __half2 h3 = __floats2half2_rn(f2, f3);
            __half2 h4 = __floats2half2_rn(u0, u1);
            __half2 h5 = __floats2half2_rn(u2, u3);
            __half2 h6 = __floats2half2_rn(v0, v1);
            __half2 h7 = __floats2half2_rn(v2, v3);
            uint32_t a0 = *(uint32_t*)&h0, a1 = *(uint32_t*)&h1;
            uint32_t a2 = *(uint32_t*)&h2, a3 = *(uint32_t*)&h3;
            uint32_t b0 = *(uint32_t*)&h4, b1 = *(uint32_t*)&h5;
            uint32_t b2 = *(uint32_t*)&h6, b3 = *(uint32_t*)&h7;

#pragma unroll
            for (int dp = 0; dp < 8; dp++) {
                uint32_t vb0, vb1, vb2, vb3;
                ldsm4(vb0, vb1, vb2, vb3,
                      vcur + (uint32_t)(dp * 4352 + ks * 32) + voff);
                mma16816(oacc0[2 * dp],     a0, a1, a2, a3, vb0, vb1);
                mma16816(oacc0[2 * dp + 1], a0, a1, a2, a3, vb2, vb3);
                mma16816(oacc1[2 * dp],     b0, b1, b2, b3, vb0, vb1);
                mma16816(oacc1[2 * dp + 1], b0, b1, b2, b3, vb2, vb3);
            }
        }

        __syncthreads();   // all warps done reading Ks/Vs[nc&1]
        if (nc < 6) {
            int n2 = (nc + 2) * 128;
            char* ksg = smraw + AT_OFF_KS0 + (nc & 1) * 10240;
            char* vsg = smraw + AT_OFF_VS0 + (nc & 1) * 34816;
            int idx = tid * 2;
#pragma unroll
            for (int i = 0; i < 2; i++) {
                int row = (idx + i) >> 2, seg = (idx + i) & 3;
                cpa16(ksg + (row * 40 + seg * 8) * 2,
                      &Kh[(size_t)(n2 + row) * KD_ + seg * 8]);
            }
#pragma unroll
            for (int i = 0; i < 8; i++) {
                int vi = tid + i * 256;
                int d = vi >> 4, seg = vi & 15;
                cpa16(vsg + (d * 136 + seg * 8) * 2,
                      &Vh[(size_t)d * N_ + n2 + seg * 8]);
            }
            CPA_COMMIT();
        }
    }

    // ---- rowsums: reduce across the quad ----
    rs0_lo += __shfl_xor_sync(0xffffffffu, rs0_lo, 1);
    rs0_lo += __shfl_xor_sync(0xffffffffu, rs0_lo, 2);
    rs0_hi += __shfl_xor_sync(0xffffffffu, rs0_hi, 1);
    rs0_hi += __shfl_xor_sync(0xffffffffu, rs0_hi, 2);
    rs1_lo += __shfl_xor_sync(0xffffffffu, rs1_lo, 1);
    rs1_lo += __shfl_xor_sync(0xffffffffu, rs1_lo, 2);
    rs1_hi += __shfl_xor_sync(0xffffffffu, rs1_hi, 1);
    rs1_hi += __shfl_xor_sync(0xffffffffu, rs1_hi, 2);
    float inv0_lo = 1.0f / rs0_lo, inv0_hi = 1.0f / rs0_hi;
    float inv1_lo = 1.0f / rs1_lo, inv1_hi = 1.0f / rs1_hi;

    // ---- epilogue: relu(O/rowsum) -> g_oh[b][m][h*128 + d] ----
    size_t row00 = (size_t)(b * N_ + m0 + w * 32 + g) * (H_ * D_) + h * D_;
    size_t row0h = row00 + (size_t)8  * (H_ * D_);
    size_t row10 = row00 + (size_t)16 * (H_ * D_);
    size_t row1h = row00 + (size_t)24 * (H_ * D_);
#pragma unroll
    for (int t = 0; t < 16; t++) {
        int d = t * 8 + tg * 2;
        __half2 p0 = __floats2half2_rn(fmaxf(oacc0[t][0] * inv0_lo, 0.f),
                                       fmaxf(oacc0[t][1] * inv0_lo, 0.f));
        __half2 p1 = __floats2half2_rn(fmaxf(oacc0[t][2] * inv0_hi, 0.f),
                                       fmaxf(oacc0[t][3] * inv0_hi, 0.f));
        __half2 p2 = __floats2half2_rn(fmaxf(oacc1[t][0] * inv1_lo, 0.f),
                                       fmaxf(oacc1[t][1] * inv1_lo, 0.f));
        __half2 p3 = __floats2half2_rn(fmaxf(oacc1[t][2] * inv1_hi, 0.f),
                                       fmaxf(oacc1[t][3] * inv1_hi, 0.f));
        *(__half2*)&g_oh[row00 + d] = p0;
        *(__half2*)&g_oh[row0h + d] = p1;
        *(__half2*)&g_oh[row10 + d] = p2;
        *(__half2*)&g_oh[row1h + d] = p3;
    }
}

// ======================================================================
// Kernel 3: out = BN(proj_w @ O + proj_b). (unchanged)
// ======================================================================
#define WT_LDS       72
#define WT_A_H       (128 * WT_LDS)
#define WT_B_H       (256 * WT_LDS)
#define WT_STAGE_B   ((WT_A_H + WT_B_H) * 2)
#define WT_SMEM_REQ  (3 * WT_STAGE_B)
#define WT_CLD       260

__global__ __launch_bounds__(512) void k_proj(const float* __restrict__ pb,
                                              const float* __restrict__ gamma,
                                              const float* __restrict__ beta,
                                              const float* __restrict__ mean,
                                              const float* __restrict__ var,
                                              float* __restrict__ out) {
    extern __shared__ __align__(16) char smraw[];
    float* Cs = (float*)smraw;

    int b   = blockIdx.z;
    int oc0 = blockIdx.y * 128;
    int n0  = blockIdx.x * 256;
    int tid = threadIdx.x;
    int wid = tid >> 5;
    int warp_m = wid >> 2, warp_n = wid & 3;

    const __half* Aw = g_pwh + (size_t)oc0 * (H_ * D_);
    const __half* Bo = g_oh + (size_t)b * N_ * (H_ * D_);

#pragma unroll
    for (int s = 0; s < 2; s++) {
        __half* As = (__half*)(smraw + s * WT_STAGE_B);
        __half* Bs = As + WT_A_H;
        int k0 = s * 64;
#pragma unroll
        for (int i = 0; i < 2; i++) {
            int idx = tid + i * 512;
            int row = idx >> 3, ch = idx & 7;
            cpa16(&As[row * WT_LDS + ch * 8], &Aw[(size_t)row * (H_ * D_) + k0 + ch * 8]);
        }
#pragma unroll
        for (int i = 0; i < 4; i++) {
            int idx = tid + i * 512;
            int row = idx >> 3, ch = idx & 7;
            cpa16(&Bs[row * WT_LDS + ch * 8], &Bo[(size_t)(n0 + row) * (H_ * D_) + k0 + ch * 8]);
        }
        CPA_COMMIT();
    }

    wmma::fragment<wmma::accumulator, 16, 16, 16, float> acc[2][4];
#pragma unroll
    for (int i = 0; i < 2; i++)
#pragma unroll
        for (int j = 0; j < 4; j++)
            wmma::fill_fragment(acc[i][j], 0.0f);

    for (int it = 0; it < 16; it++) {
        if (it == 15) { CPA_WAIT(0); } else { CPA_WAIT(1); }
        __syncthreads();

        if (it + 2 < 16) {
            int s = (it + 2) % 3;
            __half* As = (__half*)(smraw + s * WT_STAGE_B);
            __half* Bs = As + WT_A_H;
            int k0 = (it + 2) * 64;
#pragma unroll
            for (int i = 0; i < 2; i++) {
                int idx = tid + i * 512;
                int row = idx >> 3, ch = idx & 7;
                cpa16(&As[row * WT_LDS + ch * 8], &Aw[(size_t)row * (H_ * D_) + k0 + ch * 8]);
            }
#pragma unroll
            for (int i = 0; i < 4; i++) {
                int idx = tid + i * 512;
                int row = idx >> 3, ch = idx & 7;
                cpa16(&Bs[row * WT_LDS + ch * 8], &Bo[(size_t)(n0 + row) * (H_ * D_) + k0 + ch * 8]);
            }
            CPA_COMMIT();
        }

        __half* As = (__half*)(smraw + (it % 3) * WT_STAGE_B);
        __half* Bs = As + WT_A_H;
#pragma unroll
        for (int ks = 0; ks < 4; ks++) {
            wmma::fragment<wmma::matrix_a, 16, 16, 16, __half, wmma::row_major> a[2];
            wmma::fragment<wmma::matrix_b, 16, 16, 16, __half, wmma::col_major> bf[4];
#pragma unroll
            for (int i = 0; i < 2; i++)
                wmma::load_matrix_sync(a[i], &As[(warp_m * 32 + i * 16) * WT_LDS + ks * 16], WT_LDS);
#pragma unroll
            for (int j = 0; j < 4; j++)
                wmma::load_matrix_sync(bf[j], &Bs[(warp_n * 64 + j * 16) * WT_LDS + ks * 16], WT_LDS);
#pragma unroll
            for (int i = 0; i < 2; i++)
#pragma unroll
                for (int j = 0; j < 4; j++)
                    wmma::mma_sync(acc[i][j], a[i], bf[j], acc[i][j]);
        }
    }
    __syncthreads();

#pragma unroll
    for (int i = 0; i < 2; i++)
#pragma unroll
        for (int j = 0; j < 4; j++)
            wmma::store_matrix_sync(&Cs[(warp_m * 32 + i * 16) * WT_CLD + warp_n * 64 + j * 16],
                                    acc[i][j], WT_CLD, wmma::mem_row_major);
    __syncthreads();

    int r = tid >> 2;
    int c0 = (tid & 3) * 64;
    int oc = oc0 + r;
    float bb  = pb[oc];
    float inv = gamma[oc] * rsqrtf(var[oc] + 1e-5f);
    float sh  = beta[oc] - mean[oc] * inv;
    float* orow = out + ((size_t)b * DIM_ + oc) * N_ + n0;
#pragma unroll
    for (int i = 0; i < 16; i++) {
        int c = c0 + i * 4;
        float4 v = *(float4*)&Cs[r * WT_CLD + c];
        v.x = fmaf(v.x + bb, inv, sh);
        v.y = fmaf(v.y + bb, inv, sh);
        v.z = fmaf(v.z + bb, inv, sh);
        v.w = fmaf(v.w + bb, inv, sh);
        *(float4*)&orow[c] = v;
    }
}

// ======================================================================
extern "C" void kernel_launch(void* const* d_in, const int* in_sizes, int n_in,
                              void* d_out, int out_size) {
    (void)in_sizes; (void)n_in; (void)out_size;
    const float* x      = (const float*)d_in[0];
    const float* qkv_w  = (const float*)d_in[1];
    const float* qkv_b  = (const float*)d_in[2];
    const float* proj_w = (const float*)d_in[3];
    const float* proj_b = (const float*)d_in[4];
    const float* gamma  = (const float*)d_in[5];
    const float* beta   = (const float*)d_in[6];
    const float* mean   = (const float*)d_in[7];
    const float* var    = (const float*)d_in[8];
    float* out = (float*)d_out;

    cudaFuncSetAttribute(k_qkv,  cudaFuncAttributeMaxDynamicSharedMemorySize, QK_SMEM_REQ);
    cudaFuncSetAttribute(k_attn, cudaFuncAttributeMaxDynamicSharedMemorySize, AT_SMEM_REQ);
    cudaFuncSetAttribute(k_proj, cudaFuncAttributeMaxDynamicSharedMemorySize, WT_SMEM_REQ);

    k_cvt_pw<<<512, 256>>>(proj_w);
    k_cvt_qw<<<96, 256>>>(qkv_w);

    dim3 g1(N_ / 128, BH_);
    k_qkv<<<g1, 256, QK_SMEM_REQ>>>(x, qkv_b);

    dim3 g2(N_ / 256, BH_);   // CTA covers 256 m-rows now
    k_attn<<<g2, 256, AT_SMEM_REQ>>>();

    dim3 g4(N_ / 256, DIM_ / 128, B_);
    k_proj<<<g4, 512, WT_SMEM_REQ>>>(proj_b, gamma, beta, mean, var, out);
}

// round 16
// speedup vs baseline: 1.0380x; 1.0380x over previous
#include <cuda_runtime.h>
#include <cuda_fp16.h>
#include <mma.h>
#include <cstdint>

using namespace nvcuda;

#define B_    16
#define H_    8
#define N_    1024
#define DIM_  512
#define KD_   32
#define D_    128
#define BH_   (B_*H_)

// ---- scratch (device globals; no allocations allowed) ----
__device__ __align__(16) __half g_qh[(size_t)BH_ * N_ * KD_];       // [bh][n][kd] (scaled by log2e/sqrt(32))
__device__ __align__(16) __half g_kh[(size_t)BH_ * N_ * KD_];       // [bh][n][kd]
__device__ __align__(16) __half g_vh[(size_t)BH_ * D_ * N_];        // [bh][d][n]
__device__ __align__(16) __half g_oh[(size_t)B_ * N_ * (H_*D_)];    // [b][n][c]
__device__ __align__(16) __half g_pwh[(size_t)DIM_ * (H_*D_)];      // [oc][c]
__device__ __align__(16) __half g_qwh[(size_t)H_ * 192 * 64];       // [h][o][c]

// cp.async helpers
__device__ __forceinline__ void cpa16(void* dst_smem, const void* src_gmem) {
    uint32_t d = (uint32_t)__cvta_generic_to_shared(dst_smem);
    asm volatile("cp.async.cg.shared.global [%0], [%1], 16;" :: "r"(d), "l"(src_gmem));
}
#define CPA_COMMIT()  asm volatile("cp.async.commit_group;" ::: "memory")
#define CPA_WAIT(n)   asm volatile("cp.async.wait_group %0;" :: "n"(n) : "memory")

// raw mma / ldmatrix / ex2
__device__ __forceinline__ void ldsm4(uint32_t& r0, uint32_t& r1, uint32_t& r2, uint32_t& r3,
                                      uint32_t addr) {
    asm volatile("ldmatrix.sync.aligned.m8n8.x4.shared.b16 {%0,%1,%2,%3}, [%4];"
                 : "=r"(r0), "=r"(r1), "=r"(r2), "=r"(r3) : "r"(addr));
}
__device__ __forceinline__ void mma16816(float* c, uint32_t a0, uint32_t a1, uint32_t a2,
                                         uint32_t a3, uint32_t b0, uint32_t b1) {
    asm volatile("mma.sync.aligned.m16n8k16.row.col.f32.f16.f16.f32 "
                 "{%0,%1,%2,%3}, {%4,%5,%6,%7}, {%8,%9}, {%0,%1,%2,%3};"
                 : "+f"(c[0]), "+f"(c[1]), "+f"(c[2]), "+f"(c[3])
                 : "r"(a0), "r"(a1), "r"(a2), "r"(a3), "r"(b0), "r"(b1));
}
__device__ __forceinline__ float ex2f(float x) {
    float r; asm("ex2.approx.f32 %0, %1;" : "=f"(r) : "f"(x)); return r;
}

// ======================================================================
// Kernel 0a/0b: weight converts fp32 -> fp16
// ======================================================================
__global__ __launch_bounds__(256) void k_cvt_pw(const float* __restrict__ pw) {
    int idx = blockIdx.x * 256 + threadIdx.x;
    float4 v = ((const float4*)pw)[idx];
    __half2* d = (__half2*)g_pwh;
    d[idx * 2 + 0] = __floats2half2_rn(v.x, v.y);
    d[idx * 2 + 1] = __floats2half2_rn(v.z, v.w);
}
__global__ __launch_bounds__(256) void k_cvt_qw(const float* __restrict__ qw) {
    int idx = blockIdx.x * 256 + threadIdx.x;
    float4 v = ((const float4*)qw)[idx];
    __half2* d = (__half2*)g_qwh;
    d[idx * 2 + 0] = __floats2half2_rn(v.x, v.y);
    d[idx * 2 + 1] = __floats2half2_rn(v.z, v.w);
}

// ======================================================================
// Kernel 1: grouped 1x1 conv (QKV) via wmma (q scale folds log2e).
// ======================================================================
#define QK_WLD  72
#define QK_XLD  136
#define QK_CLD  132
#define QK_OFF_XS 27648
#define QK_SMEM_REQ (192 * QK_CLD * 4)

__global__ __launch_bounds__(256) void k_qkv(const float* __restrict__ x,
                                             const float* __restrict__ bias) {
    extern __shared__ __align__(16) char smraw[];
    __half* Ws = (__half*)smraw;
    __half* Xs = (__half*)(smraw + QK_OFF_XS);
    float*  Cs = (float*)smraw;

    int bh = blockIdx.y;
    int b = bh >> 3, h = bh & 7;
    int n0 = blockIdx.x * 128;
    int tid = threadIdx.x;
    int wid = tid >> 5;
    int warp_m = wid >> 1, warp_n = wid & 1;

    const __half* Wh = g_qwh + (size_t)h * 192 * 64;
    const float*  Xg = x + ((size_t)b * DIM_ + h * 64) * N_;

#pragma unroll
    for (int i = 0; i < 6; i++) {
        int idx = tid + i * 256;
        int row = idx >> 3, ch = idx & 7;
        cpa16(&Ws[row * QK_WLD + ch * 8], &Wh[(size_t)row * 64 + ch * 8]);
    }
    CPA_COMMIT();

#pragma unroll
    for (int i = 0; i < 4; i++) {
        int idx = tid + i * 256;
        int row = idx >> 4, g = idx & 15;
        const float4* src = (const float4*)&Xg[(size_t)row * N_ + n0 + g * 8];
        float4 v0 = src[0], v1 = src[1];
        __half2* dst = (__half2*)&Xs[row * QK_XLD + g * 8];
        dst[0] = __floats2half2_rn(v0.x, v0.y);
        dst[1] = __floats2half2_rn(v0.z, v0.w);
        dst[2] = __floats2half2_rn(v1.x, v1.y);
        dst[3] = __floats2half2_rn(v1.z, v1.w);
    }
    CPA_WAIT(0);
    __syncthreads();

    wmma::fragment<wmma::accumulator, 16, 16, 16, float> acc[3][4];
#pragma unroll
    for (int i = 0; i < 3; i++)
#pragma unroll
        for (int j = 0; j < 4; j++)
            wmma::fill_fragment(acc[i][j], 0.0f);

#pragma unroll
    for (int ks = 0; ks < 4; ks++) {
        wmma::fragment<wmma::matrix_a, 16, 16, 16, __half, wmma::row_major> a[3];
        wmma::fragment<wmma::matrix_b, 16, 16, 16, __half, wmma::row_major> bf[4];
#pragma unroll
        for (int i = 0; i < 3; i++)
            wmma::load_matrix_sync(a[i], &Ws[(warp_m * 48 + i * 16) * QK_WLD + ks * 16], QK_WLD);
#pragma unroll
        for (int j = 0; j < 4; j++)
            wmma::load_matrix_sync(bf[j], &Xs[(ks * 16) * QK_XLD + warp_n * 64 + j * 16], QK_XLD);
#pragma unroll
        for (int i = 0; i < 3; i++)
#pragma unroll
            for (int j = 0; j < 4; j++)
                wmma::mma_sync(acc[i][j], a[i], bf[j], acc[i][j]);
    }
    __syncthreads();

#pragma unroll
    for (int i = 0; i < 3; i++)
#pragma unroll
        for (int j = 0; j < 4; j++)
            wmma::store_matrix_sync(&Cs[(warp_m * 48 + i * 16) * QK_CLD + warp_n * 64 + j * 16],
                                    acc[i][j], QK_CLD, wmma::mem_row_major);
    __syncthreads();

    // log2(e)/sqrt(32): softmax done base-2 downstream
    const float SCALE = 0.2550348564624786f;
#pragma unroll
    for (int t = 0; t < 3; t++) {
        int item = tid + t * 256;
        int og = item >> 4, ng = item & 15;
        int oo0 = og * 4;
        int n = n0 + ng * 8;
        float bb[4];
#pragma unroll
        for (int r = 0; r < 4; r++) bb[r] = bias[h * 192 + oo0 + r];

        if (oo0 < 32) {
#pragma unroll
            for (int j = 0; j < 8; j++) {
                float v0 = (Cs[(oo0 + 0) * QK_CLD + ng * 8 + j] + bb[0]) * SCALE;
                float v1 = (Cs[(oo0 + 1) * QK_CLD + ng * 8 + j] + bb[1]) * SCALE;
                float v2 = (Cs[(oo0 + 2) * QK_CLD + ng * 8 + j] + bb[2]) * SCALE;
                float v3 = (Cs[(oo0 + 3) * QK_CLD + ng * 8 + j] + bb[3]) * SCALE;
                __half2* dst = (__half2*)&g_qh[((size_t)bh * N_ + n + j) * KD_ + oo0];
                dst[0] = __floats2half2_rn(v0, v1);
                dst[1] = __floats2half2_rn(v2, v3);
            }
        } else if (oo0 < 64) {
#pragma unroll
            for (int j = 0; j < 8; j++) {
                float v0 = Cs[(oo0 + 0) * QK_CLD + ng * 8 + j] + bb[0];
                float v1 = Cs[(oo0 + 1) * QK_CLD + ng * 8 + j] + bb[1];
                float v2 = Cs[(oo0 + 2) * QK_CLD + ng * 8 + j] + bb[2];
                float v3 = Cs[(oo0 + 3) * QK_CLD + ng * 8 + j] + bb[3];
                __half2* dst = (__half2*)&g_kh[((size_t)bh * N_ + n + j) * KD_ + (oo0 - 32)];
                dst[0] = __floats2half2_rn(v0, v1);
                dst[1] = __floats2half2_rn(v2, v3);
            }
        } else {
#pragma unroll
            for (int r = 0; r < 4; r++) {
                const float* cr = &Cs[(oo0 + r) * QK_CLD + ng * 8];
                __half2* dst = (__half2*)&g_vh[((size_t)bh * D_ + (oo0 + r - 64)) * N_ + n];
                dst[0] = __floats2half2_rn(cr[0] + bb[r], cr[1] + bb[r]);
                dst[1] = __floats2half2_rn(cr[2] + bb[r], cr[3] + bb[r]);
                dst[2] = __floats2half2_rn(cr[4] + bb[r], cr[5] + bb[r]);
                dst[3] = __floats2half2_rn(cr[6] + bb[r], cr[7] + bb[r]);
            }
        }
    }
}

// ======================================================================
// Kernel 2: FUSED attention (R14 config — best measured: 138 us).
// FA2-style raw mma, interleaved S/O per k-step, P in regs (<=4 live),
// 128 regs/thread -> __launch_bounds__(256, 2) = 2 CTAs/SM.
// smem: Qs[128][40] @0 | Ks0 @10240 | Ks1 @20480 | Vs0[128][136] @30720
//       | Vs1 @65536  -> 100352 B.
// ======================================================================
#define AT_OFF_KS0 10240
#define AT_OFF_KS1 20480
#define AT_OFF_VS0 30720
#define AT_OFF_VS1 65536
#define AT_SMEM_REQ 100352

__global__ __launch_bounds__(256, 2) void k_attn() {
    extern __shared__ __align__(16) char smraw[];

    int bh = blockIdx.y;
    int b = bh >> 3, h = bh & 7;
    int m0 = blockIdx.x * 128;
    int tid = threadIdx.x;
    int w = tid >> 5, lane = tid & 31;
    int i8 = lane & 7, sub = lane >> 3;
    int g = lane >> 2, tg = lane & 3;

    const __half* Qh = g_qh + (size_t)bh * N_ * KD_;
    const __half* Kh = g_kh + (size_t)bh * N_ * KD_;
    const __half* Vh = g_vh + (size_t)bh * D_ * N_;

    uint32_t sm32 = (uint32_t)__cvta_generic_to_shared(smraw);
    uint32_t qs32 = sm32;
    uint32_t ks32b = sm32 + AT_OFF_KS0;
    uint32_t vs32b = sm32 + AT_OFF_VS0;

    // ldmatrix lane offsets (bytes)
    uint32_t qoff = (((sub & 1) * 8 + i8) * 40 + (sub >> 1) * 8) * 2;  // A: Q m16k16
    uint32_t koff = ((i8) * 40 + sub * 8) * 2;                         // B: K n-tile
    uint32_t voff = (((sub >> 1) * 8 + i8) * 136 + (sub & 1) * 8) * 2; // B: V d-pair

    // ---- prologue staging: g0 = {Q, K0, V0}, g1 = {K1, V1} ----
    {
        int idx = tid * 2;
#pragma unroll
        for (int i = 0; i < 2; i++) {
            int row = (idx + i) >> 2, seg = (idx + i) & 3;
            cpa16(smraw + (row * 40 + seg * 8) * 2, &Qh[(size_t)(m0 + row) * KD_ + seg * 8]);
            cpa16(smraw + AT_OFF_KS0 + (row * 40 + seg * 8) * 2,
                  &Kh[(size_t)row * KD_ + seg * 8]);
        }
#pragma unroll
        for (int i = 0; i < 8; i++) {
            int vi = tid + i * 256;
            int d = vi >> 4, seg = vi & 15;
            cpa16(smraw + AT_OFF_VS0 + (d * 136 + seg * 8) * 2,
                  &Vh[(size_t)d * N_ + seg * 8]);
        }
        CPA_COMMIT();
#pragma unroll
        for (int i = 0; i < 2; i++) {
            int row = (idx + i) >> 2, seg = (idx + i) & 3;
            cpa16(smraw + AT_OFF_KS1 + (row * 40 + seg * 8) * 2,
                  &Kh[(size_t)(128 + row) * KD_ + seg * 8]);
        }
#pragma unroll
        for (int i = 0; i < 8; i++) {
            int vi = tid + i * 256;
            int d = vi >> 4, seg = vi & 15;
            cpa16(smraw + AT_OFF_VS1 + (d * 136 + seg * 8) * 2,
                  &Vh[(size_t)d * N_ + 128 + seg * 8]);
        }
        CPA_COMMIT();
    }

    float oacc[16][4];
#pragma unroll
    for (int t = 0; t < 16; t++) {
        oacc[t][0] = 0.f; oacc[t][1] = 0.f; oacc[t][2] = 0.f; oacc[t][3] = 0.f;
    }
    float rs_lo = 0.f, rs_hi = 0.f;

    // Q fragments (persist whole kernel)
    uint32_t qa[8];
    CPA_WAIT(1);
    __syncthreads();
    {
        uint32_t qbase = qs32 + (uint32_t)(w * 16 * 40 * 2) + qoff;
        ldsm4(qa[0], qa[1], qa[2], qa[3], qbase);
        ldsm4(qa[4], qa[5], qa[6], qa[7], qbase + 32);
    }

#pragma unroll 1
    for (int nc = 0; nc < 8; nc++) {
        if (nc == 7) { CPA_WAIT(0); } else { CPA_WAIT(1); }
        __syncthreads();

        uint32_t kcur = ks32b + (uint32_t)((nc & 1) * 10240);
        uint32_t vcur = vs32b + (uint32_t)((nc & 1) * 34816);

        // ---- interleaved: per k-step, S for 2 n8-tiles -> exp -> O-mma sweep ----
#pragma unroll
        for (int ks = 0; ks < 8; ks++) {
            uint32_t kb0, kb1, kb2, kb3, kc0, kc1, kc2, kc3;
            ldsm4(kb0, kb1, kb2, kb3, kcur + (uint32_t)((2 * ks) * 640) + koff);
            ldsm4(kc0, kc1, kc2, kc3, kcur + (uint32_t)((2 * ks + 1) * 640) + koff);
            float c0[4] = {0.f, 0.f, 0.f, 0.f};
            float c1[4] = {0.f, 0.f, 0.f, 0.f};
            mma16816(c0, qa[0], qa[1], qa[2], qa[3], kb0, kb1);
            mma16816(c0, qa[4], qa[5], qa[6], qa[7], kb2, kb3);
            mma16816(c1, qa[0], qa[1], qa[2], qa[3], kc0, kc1);
            mma16816(c1, qa[4], qa[5], qa[6], qa[7], kc2, kc3);

            float e0 = ex2f(c0[0]), e1 = ex2f(c0[1]), e2 = ex2f(c0[2]), e3 = ex2f(c0[3]);
            float f0 = ex2f(c1[0]), f1 = ex2f(c1[1]), f2 = ex2f(c1[2]), f3 = ex2f(c1[3]);
            rs_lo += (e0 + e1) + (f0 + f1);
            rs_hi += (e2 + e3) + (f2 + f3);
            __half2 h0 = __floats2half2_rn(e0, e1);
            __half2 h1 = __floats2half2_rn(e2, e3);
            __half2 h2 = __floats2half2_rn(f0, f1);
            __half2 h3 = __floats2half2_rn(f2, f3);
            uint32_t a0 = *(uint32_t*)&h0, a1 = *(uint32_t*)&h1;
            uint32_t a2 = *(uint32_t*)&h2, a3 = *(uint32_t*)&h3;

#pragma unroll
            for (int dp = 0; dp < 8; dp++) {
                uint32_t vb0, vb1, vb2, vb3;
                ldsm4(vb0, vb1, vb2, vb3,
                      vcur + (uint32_t)(dp * 4352 + ks * 32) + voff);
                mma16816(oacc[2 * dp],     a0, a1, a2, a3, vb0, vb1);
                mma16816(oacc[2 * dp + 1], a0, a1, a2, a3, vb2, vb3);
            }
        }

        __syncthreads();   // all warps done reading Ks/Vs[nc&1]
        if (nc < 6) {
            int n2 = (nc + 2) * 128;
            char* ksg = smraw + AT_OFF_KS0 + (nc & 1) * 10240;
            char* vsg = smraw + AT_OFF_VS0 + (nc & 1) * 34816;
            int idx = tid * 2;
#pragma unroll
            for (int i = 0; i < 2; i++) {
                int row = (idx + i) >> 2, seg = (idx + i) & 3;
                cpa16(ksg + (row * 40 + seg * 8) * 2,
                      &Kh[(size_t)(n2 + row) * KD_ + seg * 8]);
            }
#pragma unroll
            for (int i = 0; i < 8; i++) {
                int vi = tid + i * 256;
                int d = vi >> 4, seg = vi & 15;
                cpa16(vsg + (d * 136 + seg * 8) * 2,
                      &Vh[(size_t)d * N_ + n2 + seg * 8]);
            }
            CPA_COMMIT();
        }
    }

    // ---- rowsums: reduce across the quad ----
    rs_lo += __shfl_xor_sync(0xffffffffu, rs_lo, 1);
    rs_lo += __shfl_xor_sync(0xffffffffu, rs_lo, 2);
    rs_hi += __shfl_xor_sync(0xffffffffu, rs_hi, 1);
    rs_hi += __shfl_xor_sync(0xffffffffu, rs_hi, 2);
    float inv_lo = 1.0f / rs_lo;
    float inv_hi = 1.0f / rs_hi;

    // ---- epilogue: relu(O/rowsum) -> g_oh[b][m][h*128 + d] ----
    size_t row_lo = (size_t)(b * N_ + m0 + w * 16 + g) * (H_ * D_) + h * D_;
    size_t row_hi = row_lo + (size_t)8 * (H_ * D_);
#pragma unroll
    for (int t = 0; t < 16; t++) {
        int d = t * 8 + tg * 2;
        __half2 lo = __floats2half2_rn(fmaxf(oacc[t][0] * inv_lo, 0.f),
                                       fmaxf(oacc[t][1] * inv_lo, 0.f));
        __half2 hi = __floats2half2_rn(fmaxf(oacc[t][2] * inv_hi, 0.f),
                                       fmaxf(oacc[t][3] * inv_hi, 0.f));
        *(__half2*)&g_oh[row_lo + d] = lo;
        *(__half2*)&g_oh[row_hi + d] = hi;
    }
}

// ======================================================================
// Kernel 3: out = BN(proj_w @ O + proj_b).
// NOW: 256 threads, 128x128 tile, TRUE 2-stage double buffer (one sync
// per iter; prefetch it+1 right after the sync), smem 36.9 KB ->
// 2 CTAs/SM (16 warps/SM). Grid (8,4,16)=512 CTAs.
// ======================================================================
#define WT_LDS       72
#define WT_STAGE_H   (128 * WT_LDS)              // halves per matrix per stage
#define WT_STAGE_B   (2 * WT_STAGE_H * 2)        // bytes per stage (A+B) = 36864
#define WT_SMEM_REQ  (2 * WT_STAGE_B)            // 73728 total? no: stages share
// NOTE: total smem = 2 stages * 36864 = 73728 B... but we need the fp32
// C epilogue buffer too; reuse stage memory (128*132*4 = 67584 <= 73728). OK.
#define WT_CLD       132

__global__ __launch_bounds__(256, 2) void k_proj(const float* __restrict__ pb,
                                                 const float* __restrict__ gamma,
                                                 const float* __restrict__ beta,
                                                 const float* __restrict__ mean,
                                                 const float* __restrict__ var,
                                                 float* __restrict__ out) {
    extern __shared__ __align__(16) char smraw[];
    float* Cs = (float*)smraw;

    int b   = blockIdx.z;
    int oc0 = blockIdx.y * 128;
    int n0  = blockIdx.x * 128;
    int tid = threadIdx.x;
    int wid = tid >> 5;
    int warp_m = wid >> 1, warp_n = wid & 1;   // 4x2 warps, 32oc x 64n

    const __half* Aw = g_pwh + (size_t)oc0 * (H_ * D_);
    const __half* Bo = g_oh + (size_t)b * N_ * (H_ * D_);

    int lrow = tid >> 3, lch = tid & 7;   // 32 rows x 8 chunks per pass

    // prologue: stage 0
    {
        __half* As = (__half*)(smraw);
        __half* Bs = As + WT_STAGE_H;
#pragma unroll
        for (int i = 0; i < 4; i++) {
            int row = lrow + i * 32;
            cpa16(&As[row * WT_LDS + lch * 8], &Aw[(size_t)row * (H_ * D_) + lch * 8]);
            cpa16(&Bs[row * WT_LDS + lch * 8], &Bo[(size_t)(n0 + row) * (H_ * D_) + lch * 8]);
        }
        CPA_COMMIT();
    }

    wmma::fragment<wmma::accumulator, 16, 16, 16, float> acc[2][4];
#pragma unroll
    for (int i = 0; i < 2; i++)
#pragma unroll
        for (int j = 0; j < 4; j++)
            wmma::fill_fragment(acc[i][j], 0.0f);

    for (int it = 0; it < 16; it++) {
        __syncthreads();   // all warps done with buffer (it+1)&1's previous contents

        if (it + 1 < 16) { // prefetch stage it+1 into the freed buffer
            int s = (it + 1) & 1;
            __half* As = (__half*)(smraw + s * WT_STAGE_B);
            __half* Bs = As + WT_STAGE_H;
            int k0 = (it + 1) * 64;
#pragma unroll
            for (int i = 0; i < 4; i++) {
                int row = lrow + i * 32;
                cpa16(&As[row * WT_LDS + lch * 8], &Aw[(size_t)row * (H_ * D_) + k0 + lch * 8]);
                cpa16(&Bs[row * WT_LDS + lch * 8], &Bo[(size_t)(n0 + row) * (H_ * D_) + k0 + lch * 8]);
            }
            CPA_COMMIT();
            CPA_WAIT(1);   // stage it landed (it+1 still in flight)
        } else {
            CPA_WAIT(0);
        }
        __syncthreads();   // staged data visible to all warps

        __half* As = (__half*)(smraw + (it & 1) * WT_STAGE_B);
        __half* Bs = As + WT_STAGE_H;
#pragma unroll
        for (int ks = 0; ks < 4; ks++) {
            wmma::fragment<wmma::matrix_a, 16, 16, 16, __half, wmma::row_major> a[2];
            wmma::fragment<wmma::matrix_b, 16, 16, 16, __half, wmma::col_major> bf[4];
#pragma unroll
            for (int i = 0; i < 2; i++)
                wmma::load_matrix_sync(a[i], &As[(warp_m * 32 + i * 16) * WT_LDS + ks * 16], WT_LDS);
#pragma unroll
            for (int j = 0; j < 4; j++)
                wmma::load_matrix_sync(bf[j], &Bs[(warp_n * 64 + j * 16) * WT_LDS + ks * 16], WT_LDS);
#pragma unroll
            for (int i = 0; i < 2; i++)
#pragma unroll
                for (int j = 0; j < 4; j++)
                    wmma::mma_sync(acc[i][j], a[i], bf[j], acc[i][j]);
        }
    }
    __syncthreads();

#pragma unroll
    for (int i = 0; i < 2; i++)
#pragma unroll
        for (int j = 0; j < 4; j++)
            wmma::store_matrix_sync(&Cs[(warp_m * 32 + i * 16) * WT_CLD + warp_n * 64 + j * 16],
                                    acc[i][j], WT_CLD, wmma::mem_row_major);
    __syncthreads();

    int r = tid >> 1;                 // 0..127 oc rows, 2 threads/row
    int c0 = (tid & 1) * 64;
    int oc = oc0 + r;
    float bb  = pb[oc];
    float inv = gamma[oc] * rsqrtf(var[oc] + 1e-5f);
    float sh  = beta[oc] - mean[oc] * inv;
    float* orow = out + ((size_t)b * DIM_ + oc) * N_ + n0;
#pragma unroll
    for (int i = 0; i < 16; i++) {
        int c = c0 + i * 4;
        float4 v = *(float4*)&Cs[r * WT_CLD + c];
        v.x = fmaf(v.x + bb, inv, sh);
        v.y = fmaf(v.y + bb, inv, sh);
        v.z = fmaf(v.z + bb, inv, sh);
        v.w = fmaf(v.w + bb, inv, sh);
        *(float4*)&orow[c] = v;
    }
}

// ======================================================================
extern "C" void kernel_launch(void* const* d_in, const int* in_sizes, int n_in,
                              void* d_out, int out_size) {
    (void)in_sizes; (void)n_in; (void)out_size;
    const float* x      = (const float*)d_in[0];
    const float* qkv_w  = (const float*)d_in[1];
    const float* qkv_b  = (const float*)d_in[2];
    const float* proj_w = (const float*)d_in[3];
    const float* proj_b = (const float*)d_in[4];
    const float* gamma  = (const float*)d_in[5];
    const float* beta   = (const float*)d_in[6];
    const float* mean   = (const float*)d_in[7];
    const float* var    = (const float*)d_in[8];
    float* out = (float*)d_out;

    cudaFuncSetAttribute(k_qkv,  cudaFuncAttributeMaxDynamicSharedMemorySize, QK_SMEM_REQ);
    cudaFuncSetAttribute(k_attn, cudaFuncAttributeMaxDynamicSharedMemorySize, AT_SMEM_REQ);
    cudaFuncSetAttribute(k_proj, cudaFuncAttributeMaxDynamicSharedMemorySize, WT_SMEM_REQ);

    k_cvt_pw<<<512, 256>>>(proj_w);
    k_cvt_qw<<<96, 256>>>(qkv_w);

    dim3 g1(N_ / 128, BH_);
    k_qkv<<<g1, 256, QK_SMEM_REQ>>>(x, qkv_b);

    dim3 g2(N_ / 128, BH_);
    k_attn<<<g2, 256, AT_SMEM_REQ>>>();

    dim3 g4(N_ / 128, DIM_ / 128, B_);
    k_proj<<<g4, 256, WT_SMEM_REQ>>>(proj_b, gamma, beta, mean, var, out);
}

// round 17
// speedup vs baseline: 1.0452x; 1.0069x over previous
#include <cuda_runtime.h>
#include <cuda_fp16.h>
#include <mma.h>
#include <cstdint>

using namespace nvcuda;

#define B_    16
#define H_    8
#define N_    1024
#define DIM_  512
#define KD_   32
#define D_    128
#define BH_   (B_*H_)

// ---- scratch (device globals; no allocations allowed) ----
__device__ __align__(16) __half g_qh[(size_t)BH_ * N_ * KD_];       // [bh][n][kd] (scaled by log2e/sqrt(32))
__device__ __align__(16) __half g_kh[(size_t)BH_ * N_ * KD_];       // [bh][n][kd]
__device__ __align__(16) __half g_vh[(size_t)BH_ * D_ * N_];        // [bh][d][n]
__device__ __align__(16) __half g_oh[(size_t)B_ * N_ * (H_*D_)];    // [b][n][c]
__device__ __align__(16) __half g_pwh[(size_t)DIM_ * (H_*D_)];      // [oc][c]
__device__ __align__(16) __half g_qwh[(size_t)H_ * 192 * 64];       // [h][o][c]

// cp.async helpers
__device__ __forceinline__ void cpa16(void* dst_smem, const void* src_gmem) {
    uint32_t d = (uint32_t)__cvta_generic_to_shared(dst_smem);
    asm volatile("cp.async.cg.shared.global [%0], [%1], 16;" :: "r"(d), "l"(src_gmem));
}
#define CPA_COMMIT()  asm volatile("cp.async.commit_group;" ::: "memory")
#define CPA_WAIT(n)   asm volatile("cp.async.wait_group %0;" :: "n"(n) : "memory")

// raw mma / ldmatrix / ex2
__device__ __forceinline__ void ldsm4(uint32_t& r0, uint32_t& r1, uint32_t& r2, uint32_t& r3,
                                      uint32_t addr) {
    asm volatile("ldmatrix.sync.aligned.m8n8.x4.shared.b16 {%0,%1,%2,%3}, [%4];"
                 : "=r"(r0), "=r"(r1), "=r"(r2), "=r"(r3) : "r"(addr));
}
__device__ __forceinline__ void mma16816(float* c, uint32_t a0, uint32_t a1, uint32_t a2,
                                         uint32_t a3, uint32_t b0, uint32_t b1) {
    asm volatile("mma.sync.aligned.m16n8k16.row.col.f32.f16.f16.f32 "
                 "{%0,%1,%2,%3}, {%4,%5,%6,%7}, {%8,%9}, {%0,%1,%2,%3};"
                 : "+f"(c[0]), "+f"(c[1]), "+f"(c[2]), "+f"(c[3])
                 : "r"(a0), "r"(a1), "r"(a2), "r"(a3), "r"(b0), "r"(b1));
}
__device__ __forceinline__ float ex2f(float x) {
    float r; asm("ex2.approx.f32 %0, %1;" : "=f"(r) : "f"(x)); return r;
}

// ======================================================================
// Kernel 0a/0b: weight converts fp32 -> fp16
// ======================================================================
__global__ __launch_bounds__(256) void k_cvt_pw(const float* __restrict__ pw) {
    int idx = blockIdx.x * 256 + threadIdx.x;
    float4 v = ((const float4*)pw)[idx];
    __half2* d = (__half2*)g_pwh;
    d[idx * 2 + 0] = __floats2half2_rn(v.x, v.y);
    d[idx * 2 + 1] = __floats2half2_rn(v.z, v.w);
}
__global__ __launch_bounds__(256) void k_cvt_qw(const float* __restrict__ qw) {
    int idx = blockIdx.x * 256 + threadIdx.x;
    float4 v = ((const float4*)qw)[idx];
    __half2* d = (__half2*)g_qwh;
    d[idx * 2 + 0] = __floats2half2_rn(v.x, v.y);
    d[idx * 2 + 1] = __floats2half2_rn(v.z, v.w);
}

// ======================================================================
// Kernel 1: grouped 1x1 conv (QKV) via wmma (q scale folds log2e).
// ======================================================================
#define QK_WLD  72
#define QK_XLD  136
#define QK_CLD  132
#define QK_OFF_XS 27648
#define QK_SMEM_REQ (192 * QK_CLD * 4)

__global__ __launch_bounds__(256) void k_qkv(const float* __restrict__ x,
                                             const float* __restrict__ bias) {
    extern __shared__ __align__(16) char smraw[];
    __half* Ws = (__half*)smraw;
    __half* Xs = (__half*)(smraw + QK_OFF_XS);
    float*  Cs = (float*)smraw;

    int bh = blockIdx.y;
    int b = bh >> 3, h = bh & 7;
    int n0 = blockIdx.x * 128;
    int tid = threadIdx.x;
    int wid = tid >> 5;
    int warp_m = wid >> 1, warp_n = wid & 1;

    const __half* Wh = g_qwh + (size_t)h * 192 * 64;
    const float*  Xg = x + ((size_t)b * DIM_ + h * 64) * N_;

#pragma unroll
    for (int i = 0; i < 6; i++) {
        int idx = tid + i * 256;
        int row = idx >> 3, ch = idx & 7;
        cpa16(&Ws[row * QK_WLD + ch * 8], &Wh[(size_t)row * 64 + ch * 8]);
    }
    CPA_COMMIT();

#pragma unroll
    for (int i = 0; i < 4; i++) {
        int idx = tid + i * 256;
        int row = idx >> 4, g = idx & 15;
        const float4* src = (const float4*)&Xg[(size_t)row * N_ + n0 + g * 8];
        float4 v0 = src[0], v1 = src[1];
        __half2* dst = (__half2*)&Xs[row * QK_XLD + g * 8];
        dst[0] = __floats2half2_rn(v0.x, v0.y);
        dst[1] = __floats2half2_rn(v0.z, v0.w);
        dst[2] = __floats2half2_rn(v1.x, v1.y);
        dst[3] = __floats2half2_rn(v1.z, v1.w);
    }
    CPA_WAIT(0);
    __syncthreads();

    wmma::fragment<wmma::accumulator, 16, 16, 16, float> acc[3][4];
#pragma unroll
    for (int i = 0; i < 3; i++)
#pragma unroll
        for (int j = 0; j < 4; j++)
            wmma::fill_fragment(acc[i][j], 0.0f);

#pragma unroll
    for (int ks = 0; ks < 4; ks++) {
        wmma::fragment<wmma::matrix_a, 16, 16, 16, __half, wmma::row_major> a[3];
        wmma::fragment<wmma::matrix_b, 16, 16, 16, __half, wmma::row_major> bf[4];
#pragma unroll
        for (int i = 0; i < 3; i++)
            wmma::load_matrix_sync(a[i], &Ws[(warp_m * 48 + i * 16) * QK_WLD + ks * 16], QK_WLD);
#pragma unroll
        for (int j = 0; j < 4; j++)
            wmma::load_matrix_sync(bf[j], &Xs[(ks * 16) * QK_XLD + warp_n * 64 + j * 16], QK_XLD);
#pragma unroll
        for (int i = 0; i < 3; i++)
#pragma unroll
            for (int j = 0; j < 4; j++)
                wmma::mma_sync(acc[i][j], a[i], bf[j], acc[i][j]);
    }
    __syncthreads();

#pragma unroll
    for (int i = 0; i < 3; i++)
#pragma unroll
        for (int j = 0; j < 4; j++)
            wmma::store_matrix_sync(&Cs[(warp_m * 48 + i * 16) * QK_CLD + warp_n * 64 + j * 16],
                                    acc[i][j], QK_CLD, wmma::mem_row_major);
    __syncthreads();

    // log2(e)/sqrt(32): softmax done base-2 downstream
    const float SCALE = 0.2550348564624786f;
#pragma unroll
    for (int t = 0; t < 3; t++) {
        int item = tid + t * 256;
        int og = item >> 4, ng = item & 15;
        int oo0 = og * 4;
        int n = n0 + ng * 8;
        float bb[4];
#pragma unroll
        for (int r = 0; r < 4; r++) bb[r] = bias[h * 192 + oo0 + r];

        if (oo0 < 32) {
#pragma unroll
            for (int j = 0; j < 8; j++) {
                float v0 = (Cs[(oo0 + 0) * QK_CLD + ng * 8 + j] + bb[0]) * SCALE;
                float v1 = (Cs[(oo0 + 1) * QK_CLD + ng * 8 + j] + bb[1]) * SCALE;
                float v2 = (Cs[(oo0 + 2) * QK_CLD + ng * 8 + j] + bb[2]) * SCALE;
                float v3 = (Cs[(oo0 + 3) * QK_CLD + ng * 8 + j] + bb[3]) * SCALE;
                __half2* dst = (__half2*)&g_qh[((size_t)bh * N_ + n + j) * KD_ + oo0];
                dst[0] = __floats2half2_rn(v0, v1);
                dst[1] = __floats2half2_rn(v2, v3);
            }
        } else if (oo0 < 64) {
#pragma unroll
            for (int j = 0; j < 8; j++) {
                float v0 = Cs[(oo0 + 0) * QK_CLD + ng * 8 + j] + bb[0];
                float v1 = Cs[(oo0 + 1) * QK_CLD + ng * 8 + j] + bb[1];
                float v2 = Cs[(oo0 + 2) * QK_CLD + ng * 8 + j] + bb[2];
                float v3 = Cs[(oo0 + 3) * QK_CLD + ng * 8 + j] + bb[3];
                __half2* dst = (__half2*)&g_kh[((size_t)bh * N_ + n + j) * KD_ + (oo0 - 32)];
                dst[0] = __floats2half2_rn(v0, v1);
                dst[1] = __floats2half2_rn(v2, v3);
            }
        } else {
#pragma unroll
            for (int r = 0; r < 4; r++) {
                const float* cr = &Cs[(oo0 + r) * QK_CLD + ng * 8];
                __half2* dst = (__half2*)&g_vh[((size_t)bh * D_ + (oo0 + r - 64)) * N_ + n];
                dst[0] = __floats2half2_rn(cr[0] + bb[r], cr[1] + bb[r]);
                dst[1] = __floats2half2_rn(cr[2] + bb[r], cr[3] + bb[r]);
                dst[2] = __floats2half2_rn(cr[4] + bb[r], cr[5] + bb[r]);
                dst[3] = __floats2half2_rn(cr[6] + bb[r], cr[7] + bb[r]);
            }
        }
    }
}

// ======================================================================
// Kernel 2: FUSED attention, FA2-style raw mma, PIPELINED:
//  - S(ks+1) mma issued between exp(ks) and O-mma(ks): tensor pipe gets
//    S+O back-to-back while the MUFU/pack chain overlaps.
//  - rowsum via constant fp16-ones V-row mma (fragment loaded ONCE; one
//    extra mma/ks into oaccE) -> all rowsum FADDs deleted.
// 2 CTAs/SM (128-reg cap). smem:
//   Qs[128][40] @0 | Ks0 @10240 | Ks1 @20480
//   Vs0[144][136] @30720 (rows 128..143: ones row + zeros)
//   Vs1[128][136] @69888  -> total 104704 B.
// ======================================================================
#define AT_OFF_KS0 10240
#define AT_OFF_KS1 20480
#define AT_OFF_VS0 30720
#define AT_OFF_VS1 69888
#define AT_SMEM_REQ 104704

__global__ __launch_bounds__(256, 2) void k_attn() {
    extern __shared__ __align__(16) char smraw[];

    int bh = blockIdx.y;
    int b = bh >> 3, h = bh & 7;
    int m0 = blockIdx.x * 128;
    int tid = threadIdx.x;
    int w = tid >> 5, lane = tid & 31;
    int i8 = lane & 7, sub = lane >> 3;
    int g = lane >> 2, tg = lane & 3;

    const __half* Qh = g_qh + (size_t)bh * N_ * KD_;
    const __half* Kh = g_kh + (size_t)bh * N_ * KD_;
    const __half* Vh = g_vh + (size_t)bh * D_ * N_;

    uint32_t sm32 = (uint32_t)__cvta_generic_to_shared(smraw);
    uint32_t qs32 = sm32;
    uint32_t ks32b = sm32 + AT_OFF_KS0;
    uint32_t vs32b = sm32 + AT_OFF_VS0;

    // ldmatrix lane offsets (bytes)
    uint32_t qoff = (((sub & 1) * 8 + i8) * 40 + (sub >> 1) * 8) * 2;  // A: Q m16k16
    uint32_t koff = ((i8) * 40 + sub * 8) * 2;                         // B: K n-tile
    uint32_t voff = (((sub >> 1) * 8 + i8) * 136 + (sub & 1) * 8) * 2; // B: V d-pair

    // ---- init Vs0 rows 128..143: row 128 = fp16 ones, rest zeros ----
    for (int i = tid; i < 2176; i += 256) {        // 16 rows x 68 uint32
        int row = 128 + i / 68, c2 = i % 68;
        uint32_t val = (row == 128) ? 0x3C003C00u : 0u;
        *(uint32_t*)(smraw + AT_OFF_VS0 + (size_t)(row * 136 + c2 * 2) * 2) = val;
    }

    // ---- prologue staging: g0 = {Q, K0, V0}, g1 = {K1, V1} ----
    {
        int idx = tid * 2;
#pragma unroll
        for (int i = 0; i < 2; i++) {
            int row = (idx + i) >> 2, seg = (idx + i) & 3;
            cpa16(smraw + (row * 40 + seg * 8) * 2, &Qh[(size_t)(m0 + row) * KD_ + seg * 8]);
            cpa16(smraw + AT_OFF_KS0 + (row * 40 + seg * 8) * 2,
                  &Kh[(size_t)row * KD_ + seg * 8]);
        }
#pragma unroll
        for (int i = 0; i < 8; i++) {
            int vi = tid + i * 256;
            int d = vi >> 4, seg = vi & 15;
            cpa16(smraw + AT_OFF_VS0 + (d * 136 + seg * 8) * 2,
                  &Vh[(size_t)d * N_ + seg * 8]);
        }
        CPA_COMMIT();
#pragma unroll
        for (int i = 0; i < 2; i++) {
            int row = (idx + i) >> 2, seg = (idx + i) & 3;
            cpa16(smraw + AT_OFF_KS1 + (row * 40 + seg * 8) * 2,
                  &Kh[(size_t)(128 + row) * KD_ + seg * 8]);
        }
#pragma unroll
        for (int i = 0; i < 8; i++) {
            int vi = tid + i * 256;
            int d = vi >> 4, seg = vi & 15;
            cpa16(smraw + AT_OFF_VS1 + (d * 136 + seg * 8) * 2,
                  &Vh[(size_t)d * N_ + 128 + seg * 8]);
        }
        CPA_COMMIT();
    }

    float oacc[16][4];
#pragma unroll
    for (int t = 0; t < 16; t++) {
        oacc[t][0] = 0.f; oacc[t][1] = 0.f; oacc[t][2] = 0.f; oacc[t][3] = 0.f;
    }
    float oaccE[4] = {0.f, 0.f, 0.f, 0.f};   // rowsum accumulator (d col 128)

    // Q fragments + constant ones-V fragment (persist whole kernel)
    uint32_t qa[8], vbE0, vbE1;
    CPA_WAIT(1);
    __syncthreads();
    {
        uint32_t qbase = qs32 + (uint32_t)(w * 16 * 40 * 2) + qoff;
        ldsm4(qa[0], qa[1], qa[2], qa[3], qbase);
        ldsm4(qa[4], qa[5], qa[6], qa[7], qbase + 32);
        uint32_t d2, d3;
        ldsm4(vbE0, vbE1, d2, d3, vs32b + 8 * 4352 + voff);   // rows 128..143
    }

#pragma unroll 1
    for (int nc = 0; nc < 8; nc++) {
        if (nc == 7) { CPA_WAIT(0); } else { CPA_WAIT(1); }
        __syncthreads();

        uint32_t kcur = ks32b + (uint32_t)((nc & 1) * 10240);
        uint32_t vcur = vs32b + (uint32_t)((nc & 1) * 39168);

        // ---- prologue: S(0) ----
        float cp0[4] = {0.f, 0.f, 0.f, 0.f};
        float cp1[4] = {0.f, 0.f, 0.f, 0.f};
        {
            uint32_t kb0, kb1, kb2, kb3, kc0, kc1, kc2, kc3;
            ldsm4(kb0, kb1, kb2, kb3, kcur + koff);
            ldsm4(kc0, kc1, kc2, kc3, kcur + 640 + koff);
            mma16816(cp0, qa[0], qa[1], qa[2], qa[3], kb0, kb1);
            mma16816(cp0, qa[4], qa[5], qa[6], qa[7], kb2, kb3);
            mma16816(cp1, qa[0], qa[1], qa[2], qa[3], kc0, kc1);
            mma16816(cp1, qa[4], qa[5], qa[6], qa[7], kc2, kc3);
        }

#pragma unroll
        for (int ks = 0; ks < 8; ks++) {
            // prefetch K(ks+1) fragments
            uint32_t nb0, nb1, nb2, nb3, nx0, nx1, nx2, nx3;
            if (ks < 7) {
                ldsm4(nb0, nb1, nb2, nb3, kcur + (uint32_t)((2 * ks + 2) * 640) + koff);
                ldsm4(nx0, nx1, nx2, nx3, kcur + (uint32_t)((2 * ks + 3) * 640) + koff);
            }

            // exp(ks) from cp (computed last iteration / prologue)
            float e0 = ex2f(cp0[0]), e1 = ex2f(cp0[1]), e2 = ex2f(cp0[2]), e3 = ex2f(cp0[3]);
            float f0 = ex2f(cp1[0]), f1 = ex2f(cp1[1]), f2 = ex2f(cp1[2]), f3 = ex2f(cp1[3]);
            __half2 h0 = __floats2half2_rn(e0, e1);
            __half2 h1 = __floats2half2_rn(e2, e3);
            __half2 h2 = __floats2half2_rn(f0, f1);
            __half2 h3 = __floats2half2_rn(f2, f3);
            uint32_t a0 = *(uint32_t*)&h0, a1 = *(uint32_t*)&h1;
            uint32_t a2 = *(uint32_t*)&h2, a3 = *(uint32_t*)&h3;

            // S(ks+1) mma (tensor pipe stays fed while exp/pack retire)
            if (ks < 7) {
                cp0[0] = 0.f; cp0[1] = 0.f; cp0[2] = 0.f; cp0[3] = 0.f;
                cp1[0] = 0.f; cp1[1] = 0.f; cp1[2] = 0.f; cp1[3] = 0.f;
                mma16816(cp0, qa[0], qa[1], qa[2], qa[3], nb0, nb1);
                mma16816(cp0, qa[4], qa[5], qa[6], qa[7], nb2, nb3);
                mma16816(cp1, qa[0], qa[1], qa[2], qa[3], nx0, nx1);
                mma16816(cp1, qa[4], qa[5], qa[6], qa[7], nx2, nx3);
            }

            // O(ks) sweep + rowsum mma
#pragma unroll
            for (int dp = 0; dp < 8; dp++) {
                uint32_t vb0, vb1, vb2, vb3;
                ldsm4(vb0, vb1, vb2, vb3,
                      vcur + (uint32_t)(dp * 4352 + ks * 32) + voff);
                mma16816(oacc[2 * dp],     a0, a1, a2, a3, vb0, vb1);
                mma16816(oacc[2 * dp + 1], a0, a1, a2, a3, vb2, vb3);
            }
            mma16816(oaccE, a0, a1, a2, a3, vbE0, vbE1);
        }

        __syncthreads();   // all warps done reading Ks/Vs[nc&1]
        if (nc < 6) {
            int n2 = (nc + 2) * 128;
            char* ksg = smraw + AT_OFF_KS0 + (nc & 1) * 10240;
            char* vsg = smraw + AT_OFF_VS0 + (nc & 1) * 39168;
            int idx = tid * 2;
#pragma unroll
            for (int i = 0; i < 2; i++) {
                int row = (idx + i) >> 2, seg = (idx + i) & 3;
                cpa16(ksg + (row * 40 + seg * 8) * 2,
                      &Kh[(size_t)(n2 + row) * KD_ + seg * 8]);
            }
#pragma unroll
            for (int i = 0; i < 8; i++) {
                int vi = tid + i * 256;
                int d = vi >> 4, seg = vi & 15;
                cpa16(vsg + (d * 136 + seg * 8) * 2,
                      &Vh[(size_t)d * N_ + n2 + seg * 8]);
            }
            CPA_COMMIT();
        }
    }

    // ---- rowsums live in oaccE cols (d=128 -> tg==0 lanes, c[0]/c[2]) ----
    float rlo = __shfl_sync(0xffffffffu, oaccE[0], lane & ~3);
    float rhi = __shfl_sync(0xffffffffu, oaccE[2], lane & ~3);
    float inv_lo = 1.0f / rlo;
    float inv_hi = 1.0f / rhi;

    // ---- epilogue: relu(O/rowsum) -> g_oh[b][m][h*128 + d] ----
    size_t row_lo = (size_t)(b * N_ + m0 + w * 16 + g) * (H_ * D_) + h * D_;
    size_t row_hi = row_lo + (size_t)8 * (H_ * D_);
#pragma unroll
    for (int t = 0; t < 16; t++) {
        int d = t * 8 + tg * 2;
        __half2 lo = __floats2half2_rn(fmaxf(oacc[t][0] * inv_lo, 0.f),
                                       fmaxf(oacc[t][1] * inv_lo, 0.f));
        __half2 hi = __floats2half2_rn(fmaxf(oacc[t][2] * inv_hi, 0.f),
                                       fmaxf(oacc[t][3] * inv_hi, 0.f));
        *(__half2*)&g_oh[row_lo + d] = lo;
        *(__half2*)&g_oh[row_hi + d] = hi;
    }
}

// ======================================================================
// Kernel 3: out = BN(proj_w @ O + proj_b). (unchanged from R16:
// 256 thr, 128x128, 2-stage double buffer, 2 CTAs/SM.)
// ======================================================================
#define WT_LDS       72
#define WT_STAGE_H   (128 * WT_LDS)
#define WT_STAGE_B   (2 * WT_STAGE_H * 2)
#define WT_SMEM_REQ  (2 * WT_STAGE_B)
#define WT_CLD       132

__global__ __launch_bounds__(256, 2) void k_proj(const float* __restrict__ pb,
                                                 const float* __restrict__ gamma,
                                                 const float* __restrict__ beta,
                                                 const float* __restrict__ mean,
                                                 const float* __restrict__ var,
                                                 float* __restrict__ out) {
    extern __shared__ __align__(16) char smraw[];
    float* Cs = (float*)smraw;

    int b   = blockIdx.z;
    int oc0 = blockIdx.y * 128;
    int n0  = blockIdx.x * 128;
    int tid = threadIdx.x;
    int wid = tid >> 5;
    int warp_m = wid >> 1, warp_n = wid & 1;

    const __half* Aw = g_pwh + (size_t)oc0 * (H_ * D_);
    const __half* Bo = g_oh + (size_t)b * N_ * (H_ * D_);

    int lrow = tid >> 3, lch = tid & 7;

    {
        __half* As = (__half*)(smraw);
        __half* Bs = As + WT_STAGE_H;
#pragma unroll
        for (int i = 0; i < 4; i++) {
            int row = lrow + i * 32;
            cpa16(&As[row * WT_LDS + lch * 8], &Aw[(size_t)row * (H_ * D_) + lch * 8]);
            cpa16(&Bs[row * WT_LDS + lch * 8], &Bo[(size_t)(n0 + row) * (H_ * D_) + lch * 8]);
        }
        CPA_COMMIT();
    }

    wmma::fragment<wmma::accumulator, 16, 16, 16, float> acc[2][4];
#pragma unroll
    for (int i = 0; i < 2; i++)
#pragma unroll
        for (int j = 0; j < 4; j++)
            wmma::fill_fragment(acc[i][j], 0.0f);

    for (int it = 0; it < 16; it++) {
        __syncthreads();

        if (it + 1 < 16) {
            int s = (it + 1) & 1;
            __half* As = (__half*)(smraw + s * WT_STAGE_B);
            __half* Bs = As + WT_STAGE_H;
            int k0 = (it + 1) * 64;
#pragma unroll
            for (int i = 0; i < 4; i++) {
                int row = lrow + i * 32;
                cpa16(&As[row * WT_LDS + lch * 8], &Aw[(size_t)row * (H_ * D_) + k0 + lch * 8]);
                cpa16(&Bs[row * WT_LDS + lch * 8], &Bo[(size_t)(n0 + row) * (H_ * D_) + k0 + lch * 8]);
            }
            CPA_COMMIT();
            CPA_WAIT(1);
        } else {
            CPA_WAIT(0);
        }
        __syncthreads();

        __half* As = (__half*)(smraw + (it & 1) * WT_STAGE_B);
        __half* Bs = As + WT_STAGE_H;
#pragma unroll
        for (int ks = 0; ks < 4; ks++) {
            wmma::fragment<wmma::matrix_a, 16, 16, 16, __half, wmma::row_major> a[2];
            wmma::fragment<wmma::matrix_b, 16, 16, 16, __half, wmma::col_major> bf[4];
#pragma unroll
            for (int i = 0; i < 2; i++)
                wmma::load_matrix_sync(a[i], &As[(warp_m * 32 + i * 16) * WT_LDS + ks * 16], WT_LDS);
#pragma unroll
            for (int j = 0; j < 4; j++)
                wmma::load_matrix_sync(bf[j], &Bs[(warp_n * 64 + j * 16) * WT_LDS + ks * 16], WT_LDS);
#pragma unroll
            for (int i = 0; i < 2; i++)
#pragma unroll
                for (int j = 0; j < 4; j++)
                    wmma::mma_sync(acc[i][j], a[i], bf[j], acc[i][j]);
        }
    }
    __syncthreads();

#pragma unroll
    for (int i = 0; i < 2; i++)
#pragma unroll
        for (int j = 0; j < 4; j++)
            wmma::store_matrix_sync(&Cs[(warp_m * 32 + i * 16) * WT_CLD + warp_n * 64 + j * 16],
                                    acc[i][j], WT_CLD, wmma::mem_row_major);
    __syncthreads();

    int r = tid >> 1;
    int c0 = (tid & 1) * 64;
    int oc = oc0 + r;
    float bb  = pb[oc];
    float inv = gamma[oc] * rsqrtf(var[oc] + 1e-5f);
    float sh  = beta[oc] - mean[oc] * inv;
    float* orow = out + ((size_t)b * DIM_ + oc) * N_ + n0;
#pragma unroll
    for (int i = 0; i < 16; i++) {
        int c = c0 + i * 4;
        float4 v = *(float4*)&Cs[r * WT_CLD + c];
        v.x = fmaf(v.x + bb, inv, sh);
        v.y = fmaf(v.y + bb, inv, sh);
        v.z = fmaf(v.z + bb, inv, sh);
        v.w = fmaf(v.w + bb, inv, sh);
        *(float4*)&orow[c] = v;
    }
}

// ======================================================================
extern "C" void kernel_launch(void* const* d_in, const int* in_sizes, int n_in,
                              void* d_out, int out_size) {
    (void)in_sizes; (void)n_in; (void)out_size;
    const float* x      = (const float*)d_in[0];
    const float* qkv_w  = (const float*)d_in[1];
    const float* qkv_b  = (const float*)d_in[2];
    const float* proj_w = (const float*)d_in[3];
    const float* proj_b = (const float*)d_in[4];
    const float* gamma  = (const float*)d_in[5];
    const float* beta   = (const float*)d_in[6];
    const float* mean   = (const float*)d_in[7];
    const float* var    = (const float*)d_in[8];
    float* out = (float*)d_out;

    cudaFuncSetAttribute(k_qkv,  cudaFuncAttributeMaxDynamicSharedMemorySize, QK_SMEM_REQ);
    cudaFuncSetAttribute(k_attn, cudaFuncAttributeMaxDynamicSharedMemorySize, AT_SMEM_REQ);
    cudaFuncSetAttribute(k_proj, cudaFuncAttributeMaxDynamicSharedMemorySize, WT_SMEM_REQ);

    k_cvt_pw<<<512, 256>>>(proj_w);
    k_cvt_qw<<<96, 256>>>(qkv_w);

    dim3 g1(N_ / 128, BH_);
    k_qkv<<<g1, 256, QK_SMEM_REQ>>>(x, qkv_b);

    dim3 g2(N_ / 128, BH_);
    k_attn<<<g2, 256, AT_SMEM_REQ>>>();

    dim3 g4(N_ / 128, DIM_ / 128, B_);
    k_proj<<<g4, 256, WT_SMEM_REQ>>>(proj_b, gamma, beta, mean, var, out);
}